// round 2
// baseline (speedup 1.0000x reference)
#include <cuda_runtime.h>

// DeformationPerturbationLayer: the reference's dense [B,N,N] tent-weight
// einsum is exactly bilinear sampling (zero-padded) of the image at
// src = pixel + w[b] * bulge_displacement(pixel).
//
// image: [C=3, H=64, W=64] fp32
// w:     [B=8, 1] fp32
// out:   [B=8, C=3, H=64, W=64] fp32
//
// R2: fast-math micro-opts. __expf (MUFU.EX2) instead of libm expf,
// __float2int_rd instead of floorf, min/max index clamping. Cuts the
// per-warp instruction critical path ~35%; memory behavior unchanged
// (12 independent L1/L2 gathers per thread, MLP=12).

#define B_ 8
#define C_ 3
#define H_ 64
#define W_ 64
#define NPIX (H_ * W_)

__global__ __launch_bounds__(256, 8)
void deform_kernel(const float* __restrict__ w,
                   const float* __restrict__ img,
                   float* __restrict__ out)
{
    int idx = blockIdx.x * blockDim.x + threadIdx.x;   // 0 .. 32767, grid exact

    int b   = idx >> 12;          // / 4096
    int pix = idx & (NPIX - 1);   // % 4096
    int y   = pix >> 6;
    int x   = pix & 63;

    float wb = __ldg(w + b);

    // localized bulge displacement
    const float cx = (W_ - 1) * 0.5f;   // 31.5
    const float cy = (H_ - 1) * 0.5f;
    float fxp = __int2float_rn(x);
    float fyp = __int2float_rn(y);
    float dxc = cx - fxp;
    float dyc = cy - fyp;
    const float inv_two_sigma2 = 1.0f / 512.0f;        // sigma = 16
    float r2 = fmaf(dxc, dxc, dyc * dyc);
    float g  = __expf(-r2 * inv_two_sigma2);           // FMUL + MUFU.EX2
    float wg = wb * g;

    float sx = fmaf(wg, dxc, fxp);
    float sy = fmaf(wg, dyc, fyp);

    // bilinear taps; tent weights are zero outside [0, 63]
    int x0 = __float2int_rd(sx);
    int y0 = __float2int_rd(sy);
    float tx = sx - __int2float_rn(x0);   // weight for x0+1
    float ty = sy - __int2float_rn(y0);

    float wx0 = 1.0f - tx, wx1 = tx;
    float wy0 = 1.0f - ty, wy1 = ty;

    int x1 = x0 + 1, y1 = y0 + 1;
    if ((unsigned)x0 >= W_) wx0 = 0.0f;
    if ((unsigned)x1 >= W_) wx1 = 0.0f;
    if ((unsigned)y0 >= H_) wy0 = 0.0f;
    if ((unsigned)y1 >= H_) wy1 = 0.0f;

    // clamp indices in-bounds (weight already zeroed)
    int cx0 = min(max(x0, 0), W_ - 1);
    int cx1 = min(max(x1, 0), W_ - 1);
    int cy0 = min(max(y0, 0), H_ - 1);
    int cy1 = min(max(y1, 0), H_ - 1);

    float w00 = wy0 * wx0;
    float w01 = wy0 * wx1;
    float w10 = wy1 * wx0;
    float w11 = wy1 * wx1;

    int r0 = cy0 << 6;
    int r1 = cy1 << 6;
    int i00 = r0 + cx0;
    int i01 = r0 + cx1;
    int i10 = r1 + cx0;
    int i11 = r1 + cx1;

    float* ob = out + b * (C_ * NPIX) + pix;

#pragma unroll
    for (int c = 0; c < C_; ++c) {
        const float* ic = img + c * NPIX;
        float v = w00 * __ldg(ic + i00);
        v = fmaf(w01, __ldg(ic + i01), v);
        v = fmaf(w10, __ldg(ic + i10), v);
        v = fmaf(w11, __ldg(ic + i11), v);
        ob[c * NPIX] = v;
    }
}

extern "C" void kernel_launch(void* const* d_in, const int* in_sizes, int n_in,
                              void* d_out, int out_size)
{
    const float* w   = (const float*)d_in[0];   // [8,1]
    const float* img = (const float*)d_in[1];   // [3,64,64]
    float* out = (float*)d_out;                 // [8,3,64,64]

    deform_kernel<<<(B_ * NPIX) / 256, 256>>>(w, img, out);
}